// round 6
// baseline (speedup 1.0000x reference)
#include <cuda_runtime.h>
#include <cstdint>

#define BATCH 16
#define NCLS 7
#define HH 368
#define WW 640
#define NSEG (BATCH * 6)
#define NPROD (BATCH * HH)

// Packed per-(b, class, row) stats: bits[0:10)=min col, [10:20)=max col,
// [20:31)=count (0 means empty row for this class).
__device__ unsigned g_row[NSEG * HH];
__device__ float g_bpart[BATCH];
__device__ int g_rowdone[BATCH];
__device__ int g_bdone = 0;

// ---- scoped atomics: release/acquire WITHOUT threadfence (no CCTL.IVALL) ----
__device__ __forceinline__ void red_release_add1(int* p) {
    asm volatile("red.release.gpu.global.add.s32 [%0], 1;" :: "l"(p) : "memory");
}
__device__ __forceinline__ int ld_acquire(const int* p) {
    int v;
    asm volatile("ld.acquire.gpu.global.s32 %0, [%1];" : "=r"(v) : "l"(p) : "memory");
    return v;
}
__device__ __forceinline__ int atom_add_acqrel1(int* p) {
    int old;
    asm volatile("atom.acq_rel.gpu.global.add.s32 %0, [%1], 1;"
                 : "=r"(old) : "l"(p) : "memory");
    return old;
}

__device__ __forceinline__ int pix_class(const float l[7]) {
    float e0 = __expf(l[0]);
    float e1 = __expf(l[1]);
    float e2 = __expf(l[2]);
    float e3 = __expf(l[3]);
    float e4 = __expf(l[4]);
    float e5 = __expf(l[5]);
    float e6 = __expf(l[6]);
    float den = ((e0 + e1) + (e2 + e3)) + ((e4 + e5) + e6);
    float num = e1;
    num = fmaf(2.0f, e2, num);
    num = fmaf(3.0f, e3, num);
    num = fmaf(4.0f, e4, num);
    num = fmaf(5.0f, e5, num);
    num = fmaf(6.0f, e6, num);
    // num/den in [0,6]; truncation == floor for non-negative values.
    float r = __fdividef(num, den);
    return (int)r;
}

// -------------------------------------------------------------------------
// Single kernel. Blocks [0, NPROD): producers — per-pixel class via
// soft-argmax -> packed per-row per-class (min,max,count); finish with a
// release-add on their batch counter (no fence, no L1 flush).
// Blocks [NPROD, NPROD+BATCH): consumers (scheduled in the last wave) —
// acquire-spin on the batch counter, reduce 368 rows x 6 classes via
// ordered warp trees, then the last consumer sums 16 partials in fixed
// order and writes the scalar. Counters self-reset for graph replay.
// -------------------------------------------------------------------------
__global__ __launch_bounds__(160) void k_all(float* __restrict__ out,
                                             const float* __restrict__ logits) {
    const int bid  = blockIdx.x;
    const int t    = threadIdx.x;
    const int lane = t & 31;
    const int warp = t >> 5;

    if (bid < NPROD) {
        // ---------------- producer: row stats ----------------
        const int b   = bid / HH;
        const int row = bid % HH;
        const int col0 = t << 2;   // 4 pixels per thread

        float4 v[NCLS];
#pragma unroll
        for (int c = 0; c < NCLS; c++) {
            const float* p = logits + (((size_t)b * NCLS + c) * HH + row) * WW + col0;
            v[c] = *reinterpret_cast<const float4*>(p);
        }

        int k0, k1, k2, k3;
        {
            float l[7];
#pragma unroll
            for (int c = 0; c < NCLS; c++) l[c] = v[c].x;
            k0 = pix_class(l);
#pragma unroll
            for (int c = 0; c < NCLS; c++) l[c] = v[c].y;
            k1 = pix_class(l);
#pragma unroll
            for (int c = 0; c < NCLS; c++) l[c] = v[c].z;
            k2 = pix_class(l);
#pragma unroll
            for (int c = 0; c < NCLS; c++) l[c] = v[c].w;
            k3 = pix_class(l);
        }

        // One-hot bitboard: byte j holds (1 << class_of_pixel_j).
        const unsigned B = (1u << k0) | (1u << (k1 + 8)) | (1u << (k2 + 16)) | (1u << (k3 + 24));

        __shared__ int smn[5][6], smx[5][6], sct[5][6];

#pragma unroll
        for (int c = 1; c <= 6; c++) {
            unsigned m = (B >> c) & 0x01010101u;  // bit 8*j set iff pixel j is class c
            int cnt = __popc(m);
            int mnl = m ? col0 + ((__ffs(m) - 1) >> 3) : 0x7fffffff;
            int mxl = m ? col0 + ((31 - __clz(m)) >> 3) : -1;
            int wmn = __reduce_min_sync(0xffffffffu, mnl);
            int wmx = __reduce_max_sync(0xffffffffu, mxl);
            int wct = __reduce_add_sync(0xffffffffu, cnt);
            if (lane == 0) {
                smn[warp][c - 1] = wmn;
                smx[warp][c - 1] = wmx;
                sct[warp][c - 1] = wct;
            }
        }
        __syncthreads();

        if (t < 6) {
            int fmn = 0x7fffffff, fmx = -1, fct = 0;
#pragma unroll
            for (int w = 0; w < 5; w++) {
                fmn = min(fmn, smn[w][t]);
                fmx = max(fmx, smx[w][t]);
                fct += sct[w][t];
            }
            const int idx = ((b * 6 + t) * HH) + row;
            unsigned pk = (fct == 0) ? 0u
                : ((unsigned)fmn | ((unsigned)fmx << 10) | ((unsigned)fct << 20));
            g_row[idx] = pk;
        }
        __syncthreads();
        if (t == 0) red_release_add1(&g_rowdone[b]);  // orders block's stores
        return;
    }

    // ---------------- consumer: one block per batch ----------------
    const int b = bid - NPROD;

    if (t == 0) {
        while (ld_acquire(&g_rowdone[b]) != HH) __nanosleep(64);
    }
    __syncthreads();   // acquire result published to whole block

    __shared__ float s_loss[6];

    for (int cls = warp; cls < 6; cls += 5) {
        const int base = (b * 6 + cls) * HH;

        int valid = 0, cnt = 0, S = 0;
        int fcol = 0, frow = 0, lcol = 0, lrow = 0;

        const int r0 = lane * 12;
        const int r1 = min(HH, r0 + 12);
        for (int r = r0; r < r1; r++) {
            unsigned pk = __ldcg(&g_row[base + r]);
            int c = pk >> 20;
            if (!c) continue;
            int mnv = pk & 1023;
            int mxv = (pk >> 10) & 1023;
            if (valid) {
                S += abs((mnv - r) - (lcol - lrow));
            } else {
                fcol = mnv; frow = r; valid = 1;
            }
            S += mxv - mnv;
            lcol = mxv; lrow = r; cnt += c;
        }

        // Ordered tree reduction: lane absorbs the segment from lane+off.
#pragma unroll
        for (int off = 1; off < 32; off <<= 1) {
            int ov  = __shfl_down_sync(0xffffffffu, valid, off);
            int oc  = __shfl_down_sync(0xffffffffu, cnt, off);
            int oS  = __shfl_down_sync(0xffffffffu, S, off);
            int ofc = __shfl_down_sync(0xffffffffu, fcol, off);
            int ofr = __shfl_down_sync(0xffffffffu, frow, off);
            int olc = __shfl_down_sync(0xffffffffu, lcol, off);
            int olr = __shfl_down_sync(0xffffffffu, lrow, off);
            if ((lane & (2 * off - 1)) == 0 && ov) {
                if (valid) {
                    S += oS + abs((ofc - ofr) - (lcol - lrow));
                } else {
                    S = oS; fcol = ofc; frow = ofr; valid = 1;
                }
                cnt += oc;
                lcol = olc; lrow = olr;
            }
        }

        if (lane == 0) {
            float loss = 0.0f;
            if (cnt >= 2) {
                loss = ((float)S / (float)(cnt - 1)) / (float)(cnt + 1);
            }
            s_loss[cls] = loss;
        }
    }
    __syncthreads();

    if (t == 0) {
        float bsum = ((s_loss[0] + s_loss[1]) + (s_loss[2] + s_loss[3]))
                   + (s_loss[4] + s_loss[5]);
        g_bpart[b] = bsum;
        g_rowdone[b] = 0;  // reset for next graph replay (sole reader done)
        int old = atom_add_acqrel1(&g_bdone);  // release g_bpart[b], acquire others'
        if (old == BATCH - 1) {
            float s = 0.0f;
#pragma unroll
            for (int i = 0; i < BATCH; i++) s += __ldcg(&g_bpart[i]);  // fixed order
            out[0] = s;
            g_bdone = 0;  // reset for next graph replay
        }
    }
}

extern "C" void kernel_launch(void* const* d_in, const int* in_sizes, int n_in,
                              void* d_out, int out_size) {
    const float* logits = (const float*)d_in[0];
    // d_in[1] (labels) is unused by the reference computation.
    k_all<<<NPROD + BATCH, 160>>>((float*)d_out, logits);
}

// round 7
// speedup vs baseline: 1.1263x; 1.1263x over previous
#include <cuda_runtime.h>
#include <cstdint>

#define BATCH 16
#define NCLS 7
#define HH 368
#define WW 640
#define NSEG (BATCH * 6)

// Per-(b, class, row, warp) packed stats, padded to 8 words/row (32B) for
// aligned uint4 reads. Word: bits[0:10)=min col, [10:20)=max col,
// [20:31)=count (0 means empty for this class in this warp's 128 cols).
// Only warps 0..4 are written; combine ignores slots 5..7.
__device__ unsigned g_row5[NSEG * HH * 8];
__device__ float g_part[NSEG];
__device__ int g_done = 0;

// -------------------------------------------------------------------------
// Kernel 1: per-pixel class via soft-argmax -> per-WARP per-class
// (min col, max col, count), stored directly. No smem, no __syncthreads,
// no block-level reduce: block retires as soon as its warps store.
// One block per (row, batch); 160 threads, 4 consecutive pixels each.
// -------------------------------------------------------------------------
__device__ __forceinline__ int pix_class(const float l[7]) {
    float e0 = __expf(l[0]);
    float e1 = __expf(l[1]);
    float e2 = __expf(l[2]);
    float e3 = __expf(l[3]);
    float e4 = __expf(l[4]);
    float e5 = __expf(l[5]);
    float e6 = __expf(l[6]);
    float den = ((e0 + e1) + (e2 + e3)) + ((e4 + e5) + e6);
    float num = e1;
    num = fmaf(2.0f, e2, num);
    num = fmaf(3.0f, e3, num);
    num = fmaf(4.0f, e4, num);
    num = fmaf(5.0f, e5, num);
    num = fmaf(6.0f, e6, num);
    // num/den in [0,6]; truncation == floor for non-negative values.
    float r = __fdividef(num, den);
    return (int)r;
}

__global__ __launch_bounds__(160) void k_rowstats(const float* __restrict__ logits) {
    const int row  = blockIdx.x;
    const int b    = blockIdx.y;
    const int t    = threadIdx.x;
    const int lane = t & 31;
    const int warp = t >> 5;
    const int col0 = t << 2;   // 4 pixels per thread

    float4 v[NCLS];
#pragma unroll
    for (int c = 0; c < NCLS; c++) {
        const float* p = logits + (((size_t)b * NCLS + c) * HH + row) * WW + col0;
        v[c] = *reinterpret_cast<const float4*>(p);
    }

    int k0, k1, k2, k3;
    {
        float l[7];
#pragma unroll
        for (int c = 0; c < NCLS; c++) l[c] = v[c].x;
        k0 = pix_class(l);
#pragma unroll
        for (int c = 0; c < NCLS; c++) l[c] = v[c].y;
        k1 = pix_class(l);
#pragma unroll
        for (int c = 0; c < NCLS; c++) l[c] = v[c].z;
        k2 = pix_class(l);
#pragma unroll
        for (int c = 0; c < NCLS; c++) l[c] = v[c].w;
        k3 = pix_class(l);
    }

    // One-hot bitboard: byte j holds (1 << class_of_pixel_j).
    const unsigned B = (1u << k0) | (1u << (k1 + 8)) | (1u << (k2 + 16)) | (1u << (k3 + 24));

    unsigned mypk = 0;  // lane c-1 keeps class c's packed stats

#pragma unroll
    for (int c = 1; c <= 6; c++) {
        unsigned m = (B >> c) & 0x01010101u;  // bit 8*j set iff pixel j is class c
        int cnt = __popc(m);
        int mnl = m ? col0 + ((__ffs(m) - 1) >> 3) : 0x7fffffff;
        int mxl = m ? col0 + ((31 - __clz(m)) >> 3) : -1;
        int wmn = __reduce_min_sync(0xffffffffu, mnl);
        int wmx = __reduce_max_sync(0xffffffffu, mxl);
        int wct = __reduce_add_sync(0xffffffffu, cnt);
        if (lane == c - 1) {
            mypk = (wct == 0) ? 0u
                 : ((unsigned)wmn | ((unsigned)wmx << 10) | ((unsigned)wct << 20));
        }
    }

    if (lane < 6) {
        // seg = b*6 + class(lane+1-1) = b*6 + lane
        g_row5[(((b * 6 + lane) * HH) + row) * 8 + warp] = mypk;
    }
}

// -------------------------------------------------------------------------
// Kernel 2: one block per segment (96 blocks, 384 threads). Thread r loads
// row r's 8 packed words (two aligned uint4), folds the 5 warp-stats into
// one row-stat, then ordered merges (5 warp shuffle steps + one cross-warp
// merge). Within-row contribution telescopes to (max-min); merging adjacent
// segments adds |d_first(right) - d_last(left)| with d = col - row.
// Last block sums the 96 partials in fixed order.
// -------------------------------------------------------------------------
__global__ __launch_bounds__(384) void k_combine(float* __restrict__ out) {
    const int seg  = blockIdx.x;
    const int t    = threadIdx.x;
    const int lane = t & 31;
    const int w    = t >> 5;

    int valid = 0, cnt = 0, S = 0;
    int fcol = 0, frow = 0, lcol = 0, lrow = 0;

    if (t < HH) {
        const uint4* p = reinterpret_cast<const uint4*>(&g_row5[(seg * HH + t) * 8]);
        uint4 a = p[0];
        uint4 bq = p[1];
        unsigned pks[5] = {a.x, a.y, a.z, a.w, bq.x};
        int mnv = 0x7fffffff, mxv = -1;
#pragma unroll
        for (int i = 0; i < 5; i++) {
            unsigned pk = pks[i];
            int c = pk >> 20;
            if (c) {
                cnt += c;
                mnv = min(mnv, (int)(pk & 1023));
                mxv = max(mxv, (int)((pk >> 10) & 1023));
            }
        }
        if (cnt) {
            valid = 1;
            S = mxv - mnv;
            fcol = mnv; frow = t;
            lcol = mxv; lrow = t;
        }
    }

    // Ordered warp tree: lane absorbs the segment from lane+off (its right).
#pragma unroll
    for (int off = 1; off < 32; off <<= 1) {
        int ov  = __shfl_down_sync(0xffffffffu, valid, off);
        int oc  = __shfl_down_sync(0xffffffffu, cnt, off);
        int oS  = __shfl_down_sync(0xffffffffu, S, off);
        int ofc = __shfl_down_sync(0xffffffffu, fcol, off);
        int ofr = __shfl_down_sync(0xffffffffu, frow, off);
        int olc = __shfl_down_sync(0xffffffffu, lcol, off);
        int olr = __shfl_down_sync(0xffffffffu, lrow, off);
        if ((lane & (2 * off - 1)) == 0 && ov) {
            if (valid) {
                S += oS + abs((ofc - ofr) - (lcol - lrow));
            } else {
                S = oS; fcol = ofc; frow = ofr; valid = 1;
            }
            cnt += oc;
            lcol = olc; lrow = olr;
        }
    }

    __shared__ int sv[16], sc[16], sS[16], sfc[16], sfr[16], slc[16], slr[16];
    if (t < 16) sv[t] = 0;  // pad warps 12..15 as invalid
    __syncthreads();
    if (lane == 0) {
        sv[w] = valid; sc[w] = cnt; sS[w] = S;
        sfc[w] = fcol; sfr[w] = frow; slc[w] = lcol; slr[w] = lrow;
    }
    __syncthreads();

    if (w == 0) {
        if (lane < 16) {
            valid = sv[lane]; cnt = sc[lane]; S = sS[lane];
            fcol = sfc[lane]; frow = sfr[lane]; lcol = slc[lane]; lrow = slr[lane];
        } else {
            valid = 0; cnt = 0; S = 0; fcol = frow = lcol = lrow = 0;
        }
#pragma unroll
        for (int off = 1; off < 16; off <<= 1) {
            int ov  = __shfl_down_sync(0xffffffffu, valid, off);
            int oc  = __shfl_down_sync(0xffffffffu, cnt, off);
            int oS  = __shfl_down_sync(0xffffffffu, S, off);
            int ofc = __shfl_down_sync(0xffffffffu, fcol, off);
            int ofr = __shfl_down_sync(0xffffffffu, frow, off);
            int olc = __shfl_down_sync(0xffffffffu, lcol, off);
            int olr = __shfl_down_sync(0xffffffffu, lrow, off);
            if ((lane & (2 * off - 1)) == 0 && ov) {
                if (valid) {
                    S += oS + abs((ofc - ofr) - (lcol - lrow));
                } else {
                    S = oS; fcol = ofc; frow = ofr; valid = 1;
                }
                cnt += oc;
                lcol = olc; lrow = olr;
            }
        }
        if (lane == 0) {
            float loss = 0.0f;
            if (cnt >= 2) {
                loss = ((float)S / (float)(cnt - 1)) / (float)(cnt + 1);
            }
            g_part[seg] = loss;
        }
    }

    // Last block finalizes: deterministic (integer counter, fixed sum order).
    __shared__ int s_last;
    __threadfence();
    if (t == 0) {
        int old = atomicAdd(&g_done, 1);
        s_last = (old == NSEG - 1);
    }
    __syncthreads();

    if (s_last && w == 0) {
        float v = g_part[lane] + g_part[lane + 32] + g_part[lane + 64];
#pragma unroll
        for (int off = 16; off > 0; off >>= 1)
            v += __shfl_down_sync(0xffffffffu, v, off);
        if (lane == 0) {
            out[0] = v;
            g_done = 0;  // reset for next graph replay
        }
    }
}

extern "C" void kernel_launch(void* const* d_in, const int* in_sizes, int n_in,
                              void* d_out, int out_size) {
    const float* logits = (const float*)d_in[0];
    // d_in[1] (labels) is unused by the reference computation.
    dim3 g1(HH, BATCH);
    k_rowstats<<<g1, 160>>>(logits);
    k_combine<<<NSEG, 384>>>((float*)d_out);
}